// round 4
// baseline (speedup 1.0000x reference)
#include <cuda_runtime.h>

// LQR via Riccati recursion. T=128, n_state=16, n_ctrl=8, n_all=24.
// Single CTA, 160 threads:
//  - Phase B split: warp 0 computes Qu rows (Quu,Qux,qu) then runs Cholesky+solves
//    behind __syncwarp, while warps 1-4 compute Qxx rows + qx concurrently.
//  - 3 block barriers per stage instead of 4.
//  - c-vector prefetched through a double-buffered shared staging area.
// Fix vs prior round: C stage stride is NA*NA/4 = 144 float4 (was wrongly 36).

constexpr int TT = 128, NS = 16, NC = 8, NA = 24;
constexpr int NTHR = 160;
constexpr int CST = NA * NA / 4;   // 144 float4 per stage of C

constexpr int QS = 28;  // sQ row stride (floats)
constexpr int WS = 28;  // sW row stride
constexpr int PS = 20;  // sP row stride
constexpr int AS = 17;  // Acl row stride

__device__ __align__(16) float g_K[TT][NC][NS];
__device__ float g_kk[TT][NC];
__device__ __align__(16) float g_P[TT][NS][NS];
__device__ float g_p[TT][NS];

__global__ void __launch_bounds__(NTHR, 1) lqr_kernel(
    const float* __restrict__ A, const float* __restrict__ B,
    const float* __restrict__ x0, const float* __restrict__ C,
    const float* __restrict__ c, float* __restrict__ out)
{
    extern __shared__ float sAcl[];            // [TT][NS][AS]
    __shared__ __align__(16) float sF[NS][NA]; // [A B]
    __shared__ __align__(16) float sW[NS][WS];
    __shared__ __align__(16) float sQ[NA][QS];
    __shared__ __align__(16) float sP[NS][PS];
    __shared__ __align__(16) float sK[NC][NS];
    __shared__ float sq[NA], sp[NS], skk[NC];
    __shared__ __align__(16) float scq[2][NA]; // double-buffered c_t staging
    __shared__ float sBias[TT][NS];
    __shared__ float sX[TT][NS];

    const int tid = threadIdx.x;

    for (int idx = tid; idx < NS * NA; idx += NTHR) {
        int i = idx / NA, j = idx % NA;
        sF[i][j] = (j < NS) ? A[i * NS + j] : B[i * NC + (j - NS)];
    }
    // preload c_{T-1} into buffer parity of t=TT-1
    if (tid < NA) scq[(TT - 1) & 1][tid] = c[(TT - 1) * NA + tid];
    __syncthreads();

    const float4* C4 = (const float4*)C;

    // ---- per-thread role setup + F-column register caches + first C prefetch ----
    int u_m = 0, u_jq0 = 0, u_jq1 = 0;
    int x_i = 0, x_jq = 0;
    float FcU[NS];        // warp0: F[:,NS+m]
    float Fc[NS];         // warps1-4: F[:,i]
    float4 cregU0 = {0,0,0,0}, cregU1 = {0,0,0,0}, cregA = {0,0,0,0};

    if (tid < 32) {
        u_m = (tid < 24) ? (tid & 7) : (tid - 24);
        u_jq0 = tid >> 3;          // 0,1,2 for lanes<24
        u_jq1 = u_jq0 + 3;
#pragma unroll
        for (int k = 0; k < NS; ++k) FcU[k] = sF[k][NS + u_m];
        if (tid < 24) {
            cregU0 = C4[(TT - 1) * CST + (NS + u_m) * 6 + u_jq0];
            cregU1 = C4[(TT - 1) * CST + (NS + u_m) * 6 + u_jq1];
        }
    } else {
        int task = tid - 32;
        if (task < 96) { x_i = task / 6; x_jq = task % 6; }
        else if (task < 112) { x_i = task - 96; }
        if (task < 112) {
#pragma unroll
            for (int k = 0; k < NS; ++k) Fc[k] = sF[k][x_i];
        }
        if (task < 96) cregA = C4[(TT - 1) * CST + x_i * 6 + x_jq];
    }

    // ---------------- Backward Riccati pass ----------------
#pragma unroll 1
    for (int t = TT - 1; t >= 0; --t) {
        const int par = t & 1;
        const bool notlast = (t != TT - 1);

        if (notlast) {
            // Phase A: W = P * F (96 threads, 1x4 strips)
            if (tid < 96) {
                int i = tid & 15, jq = tid >> 4;
                float4 s = make_float4(0.f, 0.f, 0.f, 0.f);
#pragma unroll
                for (int k = 0; k < NS; ++k) {
                    float p = sP[i][k];
                    float4 f = *(const float4*)&sF[k][4 * jq];
                    s.x = fmaf(p, f.x, s.x); s.y = fmaf(p, f.y, s.y);
                    s.z = fmaf(p, f.z, s.z); s.w = fmaf(p, f.w, s.w);
                }
                *(float4*)&sW[i][4 * jq] = s;
            }
            __syncthreads();
        }

        if (tid < 32) {
            // ---- warp 0: Qu rows, then Cholesky + solves ----
            if (tid < 24) {
                float4 s0 = cregU0, s1 = cregU1;
                if (notlast) {
#pragma unroll
                    for (int k = 0; k < NS; ++k) {
                        float f = FcU[k];
                        float4 w0 = *(const float4*)&sW[k][4 * u_jq0];
                        float4 w1 = *(const float4*)&sW[k][4 * u_jq1];
                        s0.x = fmaf(f, w0.x, s0.x); s0.y = fmaf(f, w0.y, s0.y);
                        s0.z = fmaf(f, w0.z, s0.z); s0.w = fmaf(f, w0.w, s0.w);
                        s1.x = fmaf(f, w1.x, s1.x); s1.y = fmaf(f, w1.y, s1.y);
                        s1.z = fmaf(f, w1.z, s1.z); s1.w = fmaf(f, w1.w, s1.w);
                    }
                }
                *(float4*)&sQ[NS + u_m][4 * u_jq0] = s0;
                *(float4*)&sQ[NS + u_m][4 * u_jq1] = s1;
            } else {
                float s = scq[par][NS + u_m];
                if (notlast) {
#pragma unroll
                    for (int k = 0; k < NS; ++k) s = fmaf(FcU[k], sp[k], s);
                }
                sq[NS + u_m] = s;
            }
            // prefetch next stage's Cu rows (independent; scoreboard-hidden)
            if (t > 0 && tid < 24) {
                cregU0 = C4[(t - 1) * CST + (NS + u_m) * 6 + u_jq0];
                cregU1 = C4[(t - 1) * CST + (NS + u_m) * 6 + u_jq1];
            }
            __syncwarp();

            // ---- Phase C+D: redundant register Cholesky + 17 solves ----
            if (tid <= NS) {
                float L[NC][NC];
                float invd[NC];
#pragma unroll
                for (int j = 0; j < NC; ++j) {
                    float d = sQ[NS + j][NS + j];
#pragma unroll
                    for (int k = 0; k < j; ++k) d = fmaf(-L[j][k], L[j][k], d);
                    float r = rsqrtf(d);
                    invd[j] = r;
#pragma unroll
                    for (int i2 = j + 1; i2 < NC; ++i2) {
                        float s = sQ[NS + i2][NS + j];
#pragma unroll
                        for (int k = 0; k < j; ++k) s = fmaf(-L[i2][k], L[j][k], s);
                        L[i2][j] = s * r;
                    }
                }
                float y[NC];
#pragma unroll
                for (int a = 0; a < NC; ++a)
                    y[a] = (tid < NS) ? sQ[NS + a][tid] : sq[NS + a];
#pragma unroll
                for (int a = 0; a < NC; ++a) {
                    float s = y[a];
#pragma unroll
                    for (int k = 0; k < a; ++k) s = fmaf(-L[a][k], y[k], s);
                    y[a] = s * invd[a];
                }
#pragma unroll
                for (int a = NC - 1; a >= 0; --a) {
                    float s = y[a];
#pragma unroll
                    for (int k = a + 1; k < NC; ++k) s = fmaf(-L[k][a], y[k], s);
                    y[a] = s * invd[a];
                }
                if (tid < NS) {
#pragma unroll
                    for (int a = 0; a < NC; ++a) { sK[a][tid] = y[a]; g_K[t][a][tid] = y[a]; }
                } else {
#pragma unroll
                    for (int a = 0; a < NC; ++a) { skk[a] = y[a]; g_kk[t][a] = y[a]; }
                }
            }
        } else {
            // ---- warps 1-4: Qxx rows + qx + c prefetch (concurrent with CD) ----
            int task = tid - 32;
            if (task < 96) {
                float4 s = cregA;
                if (notlast) {
#pragma unroll
                    for (int k = 0; k < NS; ++k) {
                        float f = Fc[k];
                        float4 w = *(const float4*)&sW[k][4 * x_jq];
                        s.x = fmaf(f, w.x, s.x); s.y = fmaf(f, w.y, s.y);
                        s.z = fmaf(f, w.z, s.z); s.w = fmaf(f, w.w, s.w);
                    }
                }
                *(float4*)&sQ[x_i][4 * x_jq] = s;
                if (t > 0) cregA = C4[(t - 1) * CST + x_i * 6 + x_jq];
            } else if (task < 112) {
                float s = scq[par][x_i];
                if (notlast) {
#pragma unroll
                    for (int k = 0; k < NS; ++k) s = fmaf(Fc[k], sp[k], s);
                }
                sq[x_i] = s;
            } else if (task >= 112 && task < 118) {
                // stage c prefetch for t-1 into the other parity buffer
                if (t > 0)
                    ((float4*)scq[1 - par])[task - 112] =
                        ((const float4*)(c + (t - 1) * NA))[task - 112];
            }
        }
        __syncthreads();

        // ---- Phase E: P, p, Acl, bias (160 threads, all independent) ----
        if (tid < 64) {                 // P = Qxx - Qxu K
            int i = tid & 15, jq = tid >> 4;
            float4 s = *(const float4*)&sQ[i][4 * jq];
#pragma unroll
            for (int m = 0; m < NC; ++m) {
                float qm = sQ[i][NS + m];
                float4 kv = *(const float4*)&sK[m][4 * jq];
                s.x = fmaf(-qm, kv.x, s.x); s.y = fmaf(-qm, kv.y, s.y);
                s.z = fmaf(-qm, kv.z, s.z); s.w = fmaf(-qm, kv.w, s.w);
            }
            *(float4*)&sP[i][4 * jq] = s;
            *(float4*)&g_P[t][i][4 * jq] = s;
        } else if (tid < 80) {          // p = qx - Qxu kk
            int i = tid - 64;
            float s = sq[i];
#pragma unroll
            for (int m = 0; m < NC; ++m) s = fmaf(-sQ[i][NS + m], skk[m], s);
            sp[i] = s; g_p[t][i] = s;
        } else if (tid < 144) {         // Acl = A - B K
            int idx = tid - 80, i = idx & 15, jq = idx >> 4;
            float4 s = *(const float4*)&sF[i][4 * jq];
#pragma unroll
            for (int m = 0; m < NC; ++m) {
                float bm = sF[i][NS + m];
                float4 kv = *(const float4*)&sK[m][4 * jq];
                s.x = fmaf(-bm, kv.x, s.x); s.y = fmaf(-bm, kv.y, s.y);
                s.z = fmaf(-bm, kv.z, s.z); s.w = fmaf(-bm, kv.w, s.w);
            }
            float* ap = &sAcl[(t * NS + i) * AS + 4 * jq];
            ap[0] = s.x; ap[1] = s.y; ap[2] = s.z; ap[3] = s.w;
        } else {                        // bias = -B kk
            int i = tid - 144;
            float s = 0.f;
#pragma unroll
            for (int m = 0; m < NC; ++m) s = fmaf(-sF[i][NS + m], skk[m], s);
            sBias[t][i] = s;
        }
        __syncthreads();
    }

    // ---------------- Forward rollout: single warp, shuffle recurrence ----------------
    if (tid < 32) {
        int i = tid & 15;
        float x = (tid < NS) ? x0[tid] : 0.f;
#pragma unroll 1
        for (int t = 0; t < TT; ++t) {
            if (tid < NS) { out[t * NA + tid] = x; sX[t][tid] = x; }
            if (t < TT - 1) {
                float s = sBias[t][i];
                const float* ar = &sAcl[(t * NS + i) * AS];
#pragma unroll
                for (int k = 0; k < NS; ++k) {
                    float xk = __shfl_sync(0xffffffffu, x, k);
                    s = fmaf(ar[k], xk, s);
                }
                x = s;
            }
        }
    }
    __syncthreads();

    // ---------------- Parallel output post-pass ----------------
    for (int idx = tid; idx < TT * NC; idx += NTHR) {
        int t = idx >> 3, m = idx & 7;
        float s = g_kk[t][m];
        const float4* Kr = (const float4*)&g_K[t][m][0];
        const float* xr = &sX[t][0];
#pragma unroll
        for (int q = 0; q < 4; ++q) {
            float4 v = Kr[q];
            s = fmaf(v.x, xr[4 * q + 0], s); s = fmaf(v.y, xr[4 * q + 1], s);
            s = fmaf(v.z, xr[4 * q + 2], s); s = fmaf(v.w, xr[4 * q + 3], s);
        }
        out[t * NA + NS + m] = -s;
    }
    for (int idx = tid; idx < TT * NS; idx += NTHR) {
        int t = idx >> 4, i = idx & 15;
        float s = g_p[t][i];
        const float4* Pr = (const float4*)&g_P[t][i][0];
        const float* xr = &sX[t][0];
#pragma unroll
        for (int q = 0; q < 4; ++q) {
            float4 v = Pr[q];
            s = fmaf(v.x, xr[4 * q + 0], s); s = fmaf(v.y, xr[4 * q + 1], s);
            s = fmaf(v.z, xr[4 * q + 2], s); s = fmaf(v.w, xr[4 * q + 3], s);
        }
        out[TT * NA + idx] = (t == 0) ? -s : s;
    }
}

extern "C" void kernel_launch(void* const* d_in, const int* in_sizes, int n_in,
                              void* d_out, int out_size) {
    const float* A  = (const float*)d_in[0];
    const float* B  = (const float*)d_in[1];
    const float* x0 = (const float*)d_in[2];
    const float* C  = (const float*)d_in[3];
    const float* c  = (const float*)d_in[4];
    float* out = (float*)d_out;

    const int dyn = TT * NS * AS * sizeof(float);  // 139264 B
    cudaFuncSetAttribute(lqr_kernel, cudaFuncAttributeMaxDynamicSharedMemorySize, dyn);
    lqr_kernel<<<1, NTHR, dyn>>>(A, B, x0, C, c, out);
}